// round 1
// baseline (speedup 1.0000x reference)
#include <cuda_runtime.h>
#include <cuda_bf16.h>

#define BH 32
#define SEQ 8192
#define D 64
#define BK 64
#define NB 128   /* q buckets (rows) */
#define NC 129   /* kv buckets + 1 (cols) */

// Scratch (device globals — no allocation allowed in kernel_launch)
__device__ float g_Sq[BH*NB*D];   // per-bucket q sums
__device__ float g_qF[BH*NB*D];   // first q element of each bucket
__device__ float g_Sk[BH*NB*D];   // per-bucket k sums
__device__ float g_Wk[BH*NB*D];   // within-bucket weighted cum-k term
__device__ float g_sq[BH*NB*D];   // final sq (pre-scaled by DIM^-0.5)
__device__ float g_skT[BH*D*NC];  // final sk, transposed per b: [b][e][col]

// ---------------------------------------------------------------------------
// Kernel A: stream q,k once. One block per (b, bucket j), 64 threads (e).
// Computes bucket sum, bucket-first element (q), and the within-bucket
// weighted running-sum term for k:  W = sum_s (partial_s / (t+1)).
// ---------------------------------------------------------------------------
__global__ void __launch_bounds__(64) kA(const float* __restrict__ q,
                                         const float* __restrict__ k) {
    int b = blockIdx.x >> 7;
    int j = blockIdx.x & 127;
    int e = threadIdx.x;
    size_t base = ((size_t)b * SEQ + (size_t)j * BK) * D + e;
    const float* qp = q + base;
    const float* kp = k + base;

    int t0 = j * BK;
    float qf = qp[0];
    float rq = qf;
    float rk = kp[0];
    float wk = rk * __fdividef(1.0f, (float)(t0 + 1));

#pragma unroll 8
    for (int s = 1; s < BK; s++) {
        float qv = qp[s * D];
        float kv = kp[s * D];
        rq += qv;
        rk += kv;
        wk += rk * __fdividef(1.0f, (float)(t0 + s + 1));
    }
    int idx = (b * NB + j) * D + e;
    g_Sq[idx] = rq;
    g_qF[idx] = qf;
    g_Sk[idx] = rk;
    g_Wk[idx] = wk;
}

// ---------------------------------------------------------------------------
// Kernel B1: per-b bucket prefix scans (length 128). One block per b.
// Stage the 4 scratch arrays (128 KB) into smem, then 64 threads scan q,
// 64 threads scan k. Emits sq (scaled by 0.125) and sk transposed.
// ---------------------------------------------------------------------------
__global__ void __launch_bounds__(256) kB1() {
    extern __shared__ float sm[];
    float* sSq = sm;
    float* sqF = sm + NB * D;
    float* sSk = sm + 2 * NB * D;
    float* sWk = sm + 3 * NB * D;
    float* sH  = sm + 4 * NB * D;   // harmonic partial sums per bucket

    int b = blockIdx.x;
    int tid = threadIdx.x;
    int base = b * NB * D;

    for (int i = tid; i < NB * D; i += 256) {
        sSq[i] = g_Sq[base + i];
        sqF[i] = g_qF[base + i];
        sSk[i] = g_Sk[base + i];
        sWk[i] = g_Wk[base + i];
    }
    if (tid < NB) {
        int t0 = tid * BK;
        float h = 0.0f;
#pragma unroll 8
        for (int s = 0; s < BK; s++)
            h += __fdividef(1.0f, (float)(t0 + s + 1));
        sH[tid] = h;
    }
    __syncthreads();

    if (tid < D) {
        // sq scan: sq[i] = (P + qfirst) / (i*64+1) * 0.125
        int e = tid;
        float acc = 0.0f;
#pragma unroll 4
        for (int j = 0; j < NB; j++) {
            float v = sSq[j * D + e];
            g_sq[base + j * D + e] =
                (acc + sqF[j * D + e]) * __fdividef(0.125f, (float)(j * BK + 1));
            acc += v;
        }
    } else if (tid < 2 * D) {
        // sk scan: sk[j] = P*H[j] + W[j]; padded with leading zero column.
        int e = tid - D;
        float acc = 0.0f;
        float* dst = g_skT + (size_t)(b * D + e) * NC;
        dst[0] = 0.0f;
#pragma unroll 4
        for (int j = 0; j < NB; j++) {
            dst[j + 1] = acc * sH[j] + sWk[j * D + e];
            acc += sSk[j * D + e];
        }
    }
}

// ---------------------------------------------------------------------------
// Kernel B2: GEMM + masked softmax + strict-lower-triangle output.
// One block per (b, 16-row tile). sk tile (64x129) and sq tile (16x64) in
// smem; each warp handles 2 rows, 5 columns per lane (jj = lane + 32c).
// ---------------------------------------------------------------------------
__global__ void __launch_bounds__(256) kB2(float* __restrict__ out) {
    __shared__ float skT[D][NC + 3];   // [64][132], cols contiguous -> conflict-free
    __shared__ float sqs[16][D];

    int b    = blockIdx.x >> 3;
    int tile = blockIdx.x & 7;
    int i0   = tile * 16;
    int tid  = threadIdx.x;

    for (int idx = tid; idx < D * NC; idx += 256) {
        int e = idx / NC, c = idx % NC;
        skT[e][c] = g_skT[(size_t)(b * D + e) * NC + c];
    }
    for (int idx = tid; idx < 16 * D; idx += 256) {
        sqs[idx >> 6][idx & 63] = g_sq[(size_t)(b * NB + i0) * D + idx];
    }
    __syncthreads();

    int w = tid >> 5, lane = tid & 31;
#pragma unroll
    for (int rr = 0; rr < 2; rr++) {
        int rl = w * 2 + rr;
        int i  = i0 + rl;

        float a0 = 0.f, a1 = 0.f, a2 = 0.f, a3 = 0.f, a4 = 0.f;
#pragma unroll 8
        for (int e = 0; e < D; e++) {
            float a = sqs[rl][e];          // broadcast
            a0 += a * skT[e][lane];
            a1 += a * skT[e][lane + 32];
            a2 += a * skT[e][lane + 64];
            a3 += a * skT[e][lane + 96];
            if (lane == 0) a4 += a * skT[e][128];
        }

        float v[5] = {a0, a1, a2, a3, a4};
        // masked max  (valid domain: jj <= i; jj=0 always valid -> m finite)
        float m = -3.402823466e+38f;
#pragma unroll
        for (int c = 0; c < 5; c++) {
            int jj = lane + 32 * c;
            if (jj <= i) m = fmaxf(m, v[c]);
        }
#pragma unroll
        for (int o = 16; o; o >>= 1)
            m = fmaxf(m, __shfl_xor_sync(0xffffffffu, m, o));

        float s = 0.0f;
#pragma unroll
        for (int c = 0; c < 5; c++) {
            int jj = lane + 32 * c;
            float ex = (jj <= i) ? __expf(v[c] - m) : 0.0f;
            v[c] = ex;
            s += ex;
        }
#pragma unroll
        for (int o = 16; o; o >>= 1)
            s += __shfl_xor_sync(0xffffffffu, s, o);
        float inv = __fdividef(1.0f, s);

        float* orow = out + ((size_t)(b * NB + i)) * NC;
#pragma unroll
        for (int c = 0; c < 5; c++) {
            int jj = lane + 32 * c;
            if (jj < NC) orow[jj] = (jj < i) ? v[c] * inv : 0.0f;
        }
    }
}

// ---------------------------------------------------------------------------
extern "C" void kernel_launch(void* const* d_in, const int* in_sizes, int n_in,
                              void* d_out, int out_size) {
    const float* q = (const float*)d_in[0];
    const float* k = (const float*)d_in[1];
    float* out = (float*)d_out;

    cudaFuncSetAttribute(kB1, cudaFuncAttributeMaxDynamicSharedMemorySize,
                         (4 * NB * D + NB) * (int)sizeof(float));

    kA<<<BH * NB, 64>>>(q, k);
    kB1<<<BH, 256, (4 * NB * D + NB) * sizeof(float)>>>();
    kB2<<<BH * 8, 256>>>(out);
}